// round 2
// baseline (speedup 1.0000x reference)
#include <cuda_runtime.h>

#define N_MAT 50000
#define N_EDGE 800000
#define D 64

// ---------------- scratch (static device memory; no allocations) ----------------
__device__ __align__(16) float g_h[N_MAT * D];       // node embeddings h
__device__ __align__(16) float g_Y[N_MAT * D];       // sum_e norm_e * X_e per dst
__device__ float g_d[N_MAT];                         // h[n] . a_cross[:64]
__device__ float g_p[N_MAT];                         // operations[op] . b[:48]
__device__ float g_expself[N_MAT];                   // exp(self score)
__device__ float g_expcross[N_EDGE];                 // exp(cross score)
__device__ float g_b[D];                             // b = W_op^T a_cross[64:]
__device__ float g_sum;                              // softmax denominator

__device__ __forceinline__ float warp_sum(float v) {
#pragma unroll
    for (int o = 16; o; o >>= 1) v += __shfl_xor_sync(0xffffffffu, v, o);
    return v;
}

// ---------------- K0: zero Y, reset sum, compute b ----------------
__global__ void k_init(const float* __restrict__ W_op, const float* __restrict__ a_cross) {
    int idx = blockIdx.x * blockDim.x + threadIdx.x;
    int stride = gridDim.x * blockDim.x;
    for (int i = idx; i < N_MAT * D; i += stride) g_Y[i] = 0.f;
    if (blockIdx.x == 0) {
        if (threadIdx.x < D) {
            float bb = 0.f;
#pragma unroll
            for (int c = 0; c < D; c++) bb += a_cross[D + c] * W_op[c * D + threadIdx.x];
            g_b[threadIdx.x] = bb;
        }
        if (threadIdx.x == D) g_sum = 0.f;
    }
}

// ---------------- K1: h = materials @ W_mat^T, d, self scores + exp partial sum ----
__global__ void __launch_bounds__(256) k_nodes(const float* __restrict__ mat,
                                               const float* __restrict__ W_mat,
                                               const float* __restrict__ a_self,
                                               const float* __restrict__ a_cross) {
    __shared__ float wt[64 * 65];   // wt[k][c] = W_mat[c][k], padded
    __shared__ float ac1[64], asc[64];
    __shared__ float spart[8];
    int tid = threadIdx.x;
    for (int e = tid; e < 4096; e += 256) {
        int c = e >> 6, k = e & 63;
        wt[k * 65 + c] = W_mat[e];
    }
    if (tid < 64) { ac1[tid] = a_cross[tid]; asc[tid] = a_self[tid] + a_self[64 + tid]; }
    __syncthreads();

    int warp = tid >> 5, lane = tid & 31;
    int row = blockIdx.x * 8 + warp;   // grid exact: 6250*8 = 50000
    float r0 = mat[row * 64 + lane];
    float r1 = mat[row * 64 + 32 + lane];
    float acc0 = 0.f, acc1 = 0.f;
#pragma unroll
    for (int k = 0; k < 64; k++) {
        float xk = __shfl_sync(0xffffffffu, (k < 32) ? r0 : r1, k & 31);
        acc0 += xk * wt[k * 65 + lane];
        acc1 += xk * wt[k * 65 + 32 + lane];
    }
    g_h[row * 64 + lane] = acc0;
    g_h[row * 64 + 32 + lane] = acc1;

    float dv = warp_sum(acc0 * ac1[lane] + acc1 * ac1[32 + lane]);
    float sv = warp_sum(acc0 * asc[lane] + acc1 * asc[32 + lane]);
    if (lane == 0) {
        g_d[row] = dv;
        float s = sv > 0.f ? sv : 0.2f * sv;        // leaky_relu(0.2)
        float ex = __expf(s);
        g_expself[row] = ex;
        spart[warp] = ex;
    }
    __syncthreads();
    if (tid == 0) {
        float t = 0.f;
#pragma unroll
        for (int i = 0; i < 8; i++) t += spart[i];
        atomicAdd(&g_sum, t);
    }
}

// ---------------- K2: p[op] = operations[op] . b[:48] ----------------
__global__ void __launch_bounds__(256) k_pops(const float* __restrict__ ops) {
    __shared__ float bs[48];
    int tid = threadIdx.x;
    if (tid < 48) bs[tid] = g_b[tid];
    __syncthreads();
    int op = blockIdx.x * 16 + (tid >> 4);   // grid exact: 3125*16 = 50000
    int j = tid & 15;
    const float* r = ops + op * 48;
    float v = r[j] * bs[j] + r[16 + j] * bs[16 + j] + r[32 + j] * bs[32 + j];
#pragma unroll
    for (int o = 8; o; o >>= 1) v += __shfl_xor_sync(0xffffffffu, v, o);
    if (j == 0) g_p[op] = v;
}

// ---------------- K3: cross scores + exp partial sum ----------------
__global__ void __launch_bounds__(256) k_escore(const float* __restrict__ ea,
                                                const int* __restrict__ ei) {
    __shared__ float b16[16];
    __shared__ float spart[8];
    int tid = threadIdx.x;
    if (tid < 16) b16[tid] = g_b[48 + tid];
    __syncthreads();
    int e = blockIdx.x * 256 + tid;          // grid exact: 3125*256 = 800000
    int src = ei[e];
    int dst = ei[N_EDGE + e];
    const float4* ea4 = (const float4*)ea;
    float s = g_d[dst] + g_p[src];
#pragma unroll
    for (int q = 0; q < 4; q++) {
        float4 v = ea4[e * 4 + q];
        s += v.x * b16[4 * q] + v.y * b16[4 * q + 1] + v.z * b16[4 * q + 2] + v.w * b16[4 * q + 3];
    }
    s = s > 0.f ? s : 0.2f * s;
    float ex = __expf(s);
    g_expcross[e] = ex;
    float wsum = warp_sum(ex);
    if ((tid & 31) == 0) spart[tid >> 5] = wsum;
    __syncthreads();
    if (tid == 0) {
        float t = 0.f;
#pragma unroll
        for (int i = 0; i < 8; i++) t += spart[i];
        atomicAdd(&g_sum, t);
    }
}

// ---------------- K4: Y[dst] += norm_e * X_e (vector red to L2) ----------------
__global__ void __launch_bounds__(256) k_accum(const float* __restrict__ ops,
                                               const float* __restrict__ ea,
                                               const int* __restrict__ ei) {
    __shared__ float s_inv;
    int tid = threadIdx.x;
    if (tid == 0) s_inv = 1.0f / g_sum;
    __syncthreads();
    int e = blockIdx.x * 16 + (tid >> 4);    // grid exact: 50000*16 = 800000
    int j = tid & 15;                        // 16 lanes x float4 = 64 components
    int src = ei[e];
    int dst = ei[N_EDGE + e];
    float norm = g_expcross[e] * s_inv;
    float4 v;
    if (j < 12) v = ((const float4*)(ops + src * 48))[j];        // components 0..47
    else        v = ((const float4*)ea)[e * 4 + (j - 12)];       // components 48..63
    v.x *= norm; v.y *= norm; v.z *= norm; v.w *= norm;
    float* p = &g_Y[dst * 64 + 4 * j];
    asm volatile("red.global.add.v4.f32 [%0], {%1,%2,%3,%4};"
                 :: "l"(p), "f"(v.x), "f"(v.y), "f"(v.z), "f"(v.w) : "memory");
}

// ---------------- K5: out = elu(norm_self*h + Y @ W_op^T) ----------------
__global__ void __launch_bounds__(256) k_final(const float* __restrict__ W_op,
                                               float* __restrict__ out) {
    __shared__ float wt[64 * 65];   // wt[k][c] = W_op[c][k]
    __shared__ float s_inv_sh;
    int tid = threadIdx.x;
    for (int e = tid; e < 4096; e += 256) {
        int c = e >> 6, k = e & 63;
        wt[k * 65 + c] = W_op[e];
    }
    if (tid == 0) s_inv_sh = 1.0f / g_sum;
    __syncthreads();
    float s_inv = s_inv_sh;

    int warp = tid >> 5, lane = tid & 31;
    int row = blockIdx.x * 8 + warp;
    float r0 = g_Y[row * 64 + lane];
    float r1 = g_Y[row * 64 + 32 + lane];
    float acc0 = 0.f, acc1 = 0.f;
#pragma unroll
    for (int k = 0; k < 64; k++) {
        float yk = __shfl_sync(0xffffffffu, (k < 32) ? r0 : r1, k & 31);
        acc0 += yk * wt[k * 65 + lane];
        acc1 += yk * wt[k * 65 + 32 + lane];
    }
    float ns = g_expself[row] * s_inv;
    float o0 = ns * g_h[row * 64 + lane] + acc0;
    float o1 = ns * g_h[row * 64 + 32 + lane] + acc1;
    o0 = o0 > 0.f ? o0 : expm1f(o0);   // elu(alpha=1)
    o1 = o1 > 0.f ? o1 : expm1f(o1);
    out[row * 64 + lane] = o0;
    out[row * 64 + 32 + lane] = o1;
}

extern "C" void kernel_launch(void* const* d_in, const int* in_sizes, int n_in,
                              void* d_out, int out_size) {
    const float* materials  = (const float*)d_in[0];
    const float* operations = (const float*)d_in[1];
    const float* edge_attr  = (const float*)d_in[2];
    const int*   edge_index = (const int*)d_in[3];
    const float* W_mat      = (const float*)d_in[4];
    const float* W_op       = (const float*)d_in[5];
    const float* a_self     = (const float*)d_in[6];
    const float* a_cross    = (const float*)d_in[7];
    float* out = (float*)d_out;

    k_init  <<<1024, 256>>>(W_op, a_cross);
    k_nodes <<<N_MAT / 8, 256>>>(materials, W_mat, a_self, a_cross);
    k_pops  <<<N_MAT / 16, 256>>>(operations);
    k_escore<<<N_EDGE / 256, 256>>>(edge_attr, edge_index);
    k_accum <<<N_EDGE / 16, 256>>>(operations, edge_attr, edge_index);
    k_final <<<N_MAT / 8, 256>>>(W_op, out);
}